// round 10
// baseline (speedup 1.0000x reference)
#include <cuda_runtime.h>
#include <cuda_bf16.h>
#include <math_constants.h>
#include <cstdint>

// ---------------------------------------------------------------------------
// PointNetConv via mma.sync bf16 m16n8k16, 3-term split (~1e-5 accuracy)
//   3x (1x1 conv -> BN(train) -> ReLU) -> max over K=64 neighbors
// Round-10: (1) W pre-split once into global uint2 pairs (GEMM just copies),
// (2) 6-op split via cvt.rn.bf16x2 + integer hi-extract (bit-identical),
// (3) 4 CTAs/SM for CIN=64 kernels: epilogue smem overlaid onto dead A
// region, 55.5KB smem, launch_bounds(256,4), X prefetch in 2x8 batches.
// ---------------------------------------------------------------------------

#define TOTAL_ROWS (16384 * 64)
#define NBLK       8192
#define NNODES     16384
#define EPS        1e-5f
#define PCOUNT     ((float)TOTAL_ROWS)

__device__ float g_h0[TOTAL_ROWS * 64];
__device__ float g_h1[TOTAL_ROWS * 64];
__device__ float g_mx[NNODES * 128];
__device__ float g_mn[NNODES * 128];
__device__ float g_psum[128 * NBLK];
__device__ float g_psq [128 * NBLK];
__device__ float g_bna[128];
__device__ float g_bnc[128];
__device__ uint2 g_wp0[64 * 32];     // pre-split W (bf16 hi/lo pairs)
__device__ uint2 g_wp1[64 * 32];
__device__ uint2 g_wp2[128 * 32];

#define AS 36   // A pair-stride (uint2): mod 16 = 4 -> conflict-free frags
#define BS 36   // B pair-stride (uint2)

// ---- smem layout (templated on CIN) ----
//  CIN==64: [bias 256][A 36864][B 18432]                    = 55552 B (4/SM)
//  CIN==67: [bias 256][We 1024][Xe 2048][A 36864][B 18432]  = 58624 B (3/SM)
template <int CIN> struct SmemOff {
    static constexpr int WE = 256;
    static constexpr int XE = (CIN == 67) ? 1280 : 256;
    static constexpr int A  = (CIN == 67) ? 3328 : 256;
    static constexpr int B  = A + 128 * AS * 8;
    static constexpr int TOTAL = B + 64 * BS * 8;
};

// fast split: two fp32 (k-even,k-odd) -> packed bf16x2 hi word + lo word
// identical rounding to scalar __float2bfloat16_rn (both cvt.rn)
static __device__ __forceinline__ uint2 split2_bf16(float v0, float v1) {
    uint32_t hi, lo;
    asm("cvt.rn.bf16x2.f32 %0, %1, %2;" : "=r"(hi) : "f"(v1), "f"(v0));
    float r0 = v0 - __uint_as_float(hi << 16);          // exact residuals
    float r1 = v1 - __uint_as_float(hi & 0xFFFF0000u);
    asm("cvt.rn.bf16x2.f32 %0, %1, %2;" : "=r"(lo) : "f"(r1), "f"(r0));
    return make_uint2(hi, lo);
}

static __device__ __forceinline__ void mma_bf16(float* c, const uint32_t* a,
                                                const uint32_t* b) {
    asm volatile(
        "mma.sync.aligned.m16n8k16.row.col.f32.bf16.bf16.f32 "
        "{%0,%1,%2,%3}, {%4,%5,%6,%7}, {%8,%9}, {%0,%1,%2,%3};"
        : "+f"(c[0]), "+f"(c[1]), "+f"(c[2]), "+f"(c[3])
        : "r"(a[0]), "r"(a[1]), "r"(a[2]), "r"(a[3]), "r"(b[0]), "r"(b[1]));
}

// ---- tiny prep: split all weights once ----
__global__ void __launch_bounds__(256) prep_w(
    const float* __restrict__ W0, const float* __restrict__ W1,
    const float* __restrict__ W2,
    uint2* __restrict__ P0, uint2* __restrict__ P1, uint2* __restrict__ P2)
{
    int idx = blockIdx.x * 256 + threadIdx.x;   // 0 .. 8192
    if (idx < 64 * 32) {
        int o = idx >> 5, pr = idx & 31;
        P0[idx] = split2_bf16(W0[o * 67 + 2 * pr], W0[o * 67 + 2 * pr + 1]);
    } else if (idx < 128 * 32) {
        int j = idx - 64 * 32;
        int o = j >> 5, pr = j & 31;
        float2 v = *(const float2*)&W1[o * 64 + 2 * pr];
        P1[j] = split2_bf16(v.x, v.y);
    } else if (idx < 256 * 32) {
        int j = idx - 128 * 32;
        int o = j >> 5, pr = j & 31;
        float2 v = *(const float2*)&W2[o * 64 + 2 * pr];
        P2[j] = split2_bf16(v.x, v.y);
    }
}

// ---------------------------------------------------------------------------
template <int CIN, bool BN_IN, bool REDUCE, int MINBLK>
__global__ void __launch_bounds__(256, MINBLK) gemm_mma(
    const float* __restrict__ X, const uint2* __restrict__ Wp,
    const float* __restrict__ Wraw,            // only for CIN==67 extras
    const float* __restrict__ B,
    const float* __restrict__ bna, const float* __restrict__ bnc,
    float* __restrict__ H, float* __restrict__ mxout, float* __restrict__ mnout,
    float* __restrict__ psum, float* __restrict__ psq)
{
    using SO = SmemOff<CIN>;
    extern __shared__ char smem[];
    float* Bsm = (float*)(smem);               // 64 f
    float* We  = (float*)(smem + SO::WE);
    float* Xe  = (float*)(smem + SO::XE);
    uint2* Ap  = (uint2*)(smem + SO::A);       // [128][AS]
    uint2* Bp  = (uint2*)(smem + SO::B);       // [64][BS]
    // epilogue buffers overlay the dead A region (guarded by syncthreads)
    float* Ps  = (float*)(smem + SO::A);           // 4*64
    float* Pq  = (float*)(smem + SO::A + 1024);
    float* Mxs = (float*)(smem + SO::A + 2048);
    float* Mns = (float*)(smem + SO::A + 3072);

    const int tid  = threadIdx.x;
    const int wid  = tid >> 5;
    const int lane = tid & 31;
    const int q = lane >> 2, s = lane & 3;
    const int bx = REDUCE ? blockIdx.y : blockIdx.x;
    const int ob = (REDUCE ? blockIdx.x : blockIdx.y) * 64;
    const long long row0 = (long long)bx * 128;
    const int rg = wid;               // row group for convert loops
    const int l2 = 2 * lane;          // fixed channel pair per thread

    if (tid < 64) Bsm[tid] = B[ob + tid];

    // BN affine for this thread's fixed channel pair
    float ba0 = 0.f, ba1 = 0.f, bc0 = 0.f, bc1 = 0.f;
    if (BN_IN) {
        float2 t = *(const float2*)&bna[l2];
        float2 u = *(const float2*)&bnc[l2];
        ba0 = t.x; ba1 = t.y; bc0 = u.x; bc1 = u.y;
    }

    // ---- W: copy pre-split pairs (n = rg + 8i, pr = lane) ----
    {
        uint2 wv[8];
#pragma unroll
        for (int i = 0; i < 8; i++)
            wv[i] = Wp[(ob + rg + 8 * i) * 32 + lane];
#pragma unroll
        for (int i = 0; i < 8; i++)
            Bp[(rg + 8 * i) * BS + lane] = wv[i];
    }

    // ---- X -> Ap pairs: 2 batches of 8 rows (keeps regs <= 64) ----
#pragma unroll
    for (int b2 = 0; b2 < 2; b2++) {
        float xv0[8], xv1[8];
#pragma unroll
        for (int i = 0; i < 8; i++) {
            int r = rg + 8 * (b2 * 8 + i);
            if (CIN == 64) {
                float2 v = *(const float2*)&X[(row0 + r) * 64 + l2];
                xv0[i] = v.x; xv1[i] = v.y;
            } else {
                xv0[i] = X[(row0 + r) * CIN + l2];
                xv1[i] = X[(row0 + r) * CIN + l2 + 1];
            }
        }
#pragma unroll
        for (int i = 0; i < 8; i++) {
            float v0 = xv0[i], v1 = xv1[i];
            if (BN_IN) {
                v0 = fmaxf(fmaf(ba0, v0, bc0), 0.0f);
                v1 = fmaxf(fmaf(ba1, v1, bc1), 0.0f);
            }
            Ap[(rg + 8 * (b2 * 8 + i)) * AS + lane] = split2_bf16(v0, v1);
        }
    }
    if (CIN == 67) {
        for (int p = tid; p < 64 * 4; p += 256) {
            int o = p >> 2, j = p & 3;
            We[p] = (j < 3) ? Wraw[(ob + o) * 67 + 64 + j] : 0.0f;
        }
        for (int p = tid; p < 128 * 4; p += 256) {
            int r = p >> 2, j = p & 3;
            Xe[p] = (j < 3) ? X[(row0 + r) * 67 + 64 + j] : 0.0f;
        }
    }
    __syncthreads();

    // ---- MMA mainloop: warp tile 32x32, K=64 in 4 k16-steps ----
    const int wr = (wid >> 1) * 32;
    const int wc = (wid & 1) * 32;

    float acc[8][4];
#pragma unroll
    for (int t = 0; t < 8; t++)
#pragma unroll
        for (int j = 0; j < 4; j++) acc[t][j] = 0.0f;

#pragma unroll
    for (int kk = 0; kk < 4; kk++) {
        const int pb = kk * 8 + s;
        uint32_t ah[2][4], al[2][4];
#pragma unroll
        for (int mt = 0; mt < 2; mt++) {
            int r0 = wr + mt * 16 + q;
            uint2 a0 = Ap[(r0    ) * AS + pb];      // k=2s,2s+1
            uint2 a1 = Ap[(r0 + 8) * AS + pb];
            uint2 a2 = Ap[(r0    ) * AS + pb + 4];  // k=2s+8,2s+9
            uint2 a3 = Ap[(r0 + 8) * AS + pb + 4];
            ah[mt][0] = a0.x; al[mt][0] = a0.y;
            ah[mt][1] = a1.x; al[mt][1] = a1.y;
            ah[mt][2] = a2.x; al[mt][2] = a2.y;
            ah[mt][3] = a3.x; al[mt][3] = a3.y;
        }
#pragma unroll
        for (int nt = 0; nt < 4; nt++) {
            int n = wc + nt * 8 + q;
            uint2 b0 = Bp[n * BS + pb];
            uint2 b1 = Bp[n * BS + pb + 4];
            uint32_t bh[2] = {b0.x, b1.x};
            uint32_t bl[2] = {b0.y, b1.y};
#pragma unroll
            for (int mt = 0; mt < 2; mt++) {
                mma_bf16(acc[mt * 4 + nt], ah[mt], bh);
                mma_bf16(acc[mt * 4 + nt], al[mt], bh);
                mma_bf16(acc[mt * 4 + nt], ah[mt], bl);
            }
        }
    }

    // ---- epilogue: bias (+L0 exact extra channels), stats, max/min ----
    float ps[8], pq[8], mxv[8], mnv[8];
#pragma unroll
    for (int t = 0; t < 8; t++) {
        ps[t] = 0.0f; pq[t] = 0.0f;
        mxv[t] = -CUDART_INF_F; mnv[t] = CUDART_INF_F;
    }

#pragma unroll
    for (int mt = 0; mt < 2; mt++) {
#pragma unroll
        for (int h = 0; h < 2; h++) {
            int r = wr + mt * 16 + q + h * 8;
            float4 xe = make_float4(0.f, 0.f, 0.f, 0.f);
            if (CIN == 67) xe = *(float4*)&Xe[r * 4];
#pragma unroll
            for (int nt = 0; nt < 4; nt++) {
                int cb = wc + nt * 8 + 2 * s;
                float v0 = acc[mt * 4 + nt][h * 2 + 0] + Bsm[cb];
                float v1 = acc[mt * 4 + nt][h * 2 + 1] + Bsm[cb + 1];
                if (CIN == 67) {
                    float4 w0 = *(float4*)&We[cb * 4];
                    float4 w1 = *(float4*)&We[(cb + 1) * 4];
                    v0 += w0.x * xe.x + w0.y * xe.y + w0.z * xe.z;
                    v1 += w1.x * xe.x + w1.y * xe.y + w1.z * xe.z;
                }
                if (!REDUCE)
                    *(float2*)&H[(row0 + r) * 64 + cb] = make_float2(v0, v1);
                int t0 = nt * 2, t1 = nt * 2 + 1;
                ps[t0] += v0; pq[t0] += v0 * v0;
                ps[t1] += v1; pq[t1] += v1 * v1;
                if (REDUCE) {
                    mxv[t0] = fmaxf(mxv[t0], v0); mnv[t0] = fminf(mnv[t0], v0);
                    mxv[t1] = fmaxf(mxv[t1], v1); mnv[t1] = fminf(mnv[t1], v1);
                }
            }
        }
    }

    // warp reduce over q (offsets 16, 8, 4)
#pragma unroll
    for (int off = 16; off >= 4; off >>= 1) {
#pragma unroll
        for (int t = 0; t < 8; t++) {
            ps[t] += __shfl_down_sync(0xffffffffu, ps[t], off);
            pq[t] += __shfl_down_sync(0xffffffffu, pq[t], off);
            if (REDUCE) {
                mxv[t] = fmaxf(mxv[t], __shfl_down_sync(0xffffffffu, mxv[t], off));
                mnv[t] = fminf(mnv[t], __shfl_down_sync(0xffffffffu, mnv[t], off));
            }
        }
    }

    __syncthreads();   // A region dead everywhere -> safe to overlay Ps/Pq/Mx/Mn
    const int wr_idx = wid >> 1;
    if (q == 0) {
#pragma unroll
        for (int t = 0; t < 8; t++) {
            int c = wc + (t >> 1) * 8 + 2 * s + (t & 1);
            Ps[wr_idx * 64 + c] = ps[t];
            Pq[wr_idx * 64 + c] = pq[t];
            if (REDUCE) {
                Mxs[wr_idx * 64 + c] = mxv[t];
                Mns[wr_idx * 64 + c] = mnv[t];
            }
        }
    }
    __syncthreads();

    if (tid < 64) {
        float sa = Ps[tid] + Ps[64 + tid] + Ps[128 + tid] + Ps[192 + tid];
        float qa = Pq[tid] + Pq[64 + tid] + Pq[128 + tid] + Pq[192 + tid];
        psum[(ob + tid) * NBLK + bx] = sa;
        psq [(ob + tid) * NBLK + bx] = qa;
    }
    if (REDUCE && tid < 128) {
        int half = tid >> 6, c = tid & 63;
        float mx = fmaxf(Mxs[(half * 2) * 64 + c], Mxs[(half * 2 + 1) * 64 + c]);
        float mn = fminf(Mns[(half * 2) * 64 + c], Mns[(half * 2 + 1) * 64 + c]);
        int node = bx * 2 + half;
        mxout[node * 128 + ob + c] = mx;
        mnout[node * 128 + ob + c] = mn;
    }
}

// ---------------------------------------------------------------------------
__global__ void __launch_bounds__(256) stats_finalize(
    const float* __restrict__ psum, const float* __restrict__ psq,
    const float* __restrict__ gamma, const float* __restrict__ beta,
    float* __restrict__ bna, float* __restrict__ bnc)
{
    const int o = blockIdx.x;
    const int tid = threadIdx.x;
    float s = 0.0f, q = 0.0f;
    for (int b = tid; b < NBLK; b += 256) {
        s += psum[o * NBLK + b];
        q += psq [o * NBLK + b];
    }
    __shared__ float sh[512];
    sh[tid] = s; sh[256 + tid] = q;
    __syncthreads();
    for (int st = 128; st > 0; st >>= 1) {
        if (tid < st) {
            sh[tid]       += sh[tid + st];
            sh[256 + tid] += sh[256 + tid + st];
        }
        __syncthreads();
    }
    if (tid == 0) {
        float mean = sh[0] / PCOUNT;
        float var  = sh[256] / PCOUNT - mean * mean;
        float a    = gamma[o] * rsqrtf(var + EPS);
        bna[o] = a;
        bnc[o] = beta[o] - mean * a;
    }
}

__global__ void __launch_bounds__(256) apply_out(
    const float* __restrict__ mx, const float* __restrict__ mn,
    const float* __restrict__ bna, const float* __restrict__ bnc,
    float* __restrict__ out)
{
    int idx = blockIdx.x * 256 + threadIdx.x;
    int c = idx & 127;
    float a = bna[c];
    float h = (a > 0.0f) ? mx[idx] : mn[idx];
    out[idx] = fmaxf(fmaf(a, h, bnc[c]), 0.0f);
}

// ---------------------------------------------------------------------------
extern "C" void kernel_launch(void* const* d_in, const int* in_sizes, int n_in,
                              void* d_out, int out_size)
{
    const float* x   = (const float*)d_in[0];
    const float* w0  = (const float*)d_in[1];
    const float* b0  = (const float*)d_in[2];
    const float* gm0 = (const float*)d_in[3];
    const float* be0 = (const float*)d_in[4];
    const float* w1  = (const float*)d_in[5];
    const float* b1  = (const float*)d_in[6];
    const float* gm1 = (const float*)d_in[7];
    const float* be1 = (const float*)d_in[8];
    const float* w2  = (const float*)d_in[9];
    const float* b2  = (const float*)d_in[10];
    const float* gm2 = (const float*)d_in[11];
    const float* be2 = (const float*)d_in[12];
    float* out = (float*)d_out;

    float *h0, *h1, *mx, *mn, *psum, *psq, *bna, *bnc;
    uint2 *wp0, *wp1, *wp2;
    cudaGetSymbolAddress((void**)&h0,   g_h0);
    cudaGetSymbolAddress((void**)&h1,   g_h1);
    cudaGetSymbolAddress((void**)&mx,   g_mx);
    cudaGetSymbolAddress((void**)&mn,   g_mn);
    cudaGetSymbolAddress((void**)&psum, g_psum);
    cudaGetSymbolAddress((void**)&psq,  g_psq);
    cudaGetSymbolAddress((void**)&bna,  g_bna);
    cudaGetSymbolAddress((void**)&bnc,  g_bnc);
    cudaGetSymbolAddress((void**)&wp0,  g_wp0);
    cudaGetSymbolAddress((void**)&wp1,  g_wp1);
    cudaGetSymbolAddress((void**)&wp2,  g_wp2);

    constexpr int ST67 = SmemOff<67>::TOTAL;   // 58624 -> 3 CTAs/SM
    constexpr int ST64 = SmemOff<64>::TOTAL;   // 55552 -> 4 CTAs/SM
    cudaFuncSetAttribute(gemm_mma<67, false, false, 3>,
                         cudaFuncAttributeMaxDynamicSharedMemorySize, ST67);
    cudaFuncSetAttribute(gemm_mma<64, true, false, 4>,
                         cudaFuncAttributeMaxDynamicSharedMemorySize, ST64);
    cudaFuncSetAttribute(gemm_mma<64, true, true, 4>,
                         cudaFuncAttributeMaxDynamicSharedMemorySize, ST64);

    // launch #1: pre-split weights (also shifts ncu -s 5 onto a GEMM)
    prep_w<<<32, 256>>>(w0, w1, w2, wp0, wp1, wp2);

    // L0: conv(67->64) + stats
    gemm_mma<67, false, false, 3><<<dim3(NBLK, 1), 256, ST67>>>(
        x, wp0, w0, b0, nullptr, nullptr, h0, nullptr, nullptr, psum, psq);
    stats_finalize<<<64, 256>>>(psum, psq, gm0, be0, bna, bnc);

    // L1: bn0+relu on load -> conv(64->64) + stats
    gemm_mma<64, true, false, 4><<<dim3(NBLK, 1), 256, ST64>>>(
        h0, wp1, nullptr, b1, bna, bnc, h1, nullptr, nullptr, psum, psq);
    stats_finalize<<<64, 256>>>(psum, psq, gm1, be1, bna, bnc);

    // L2: bn1+relu on load -> conv(64->128, grid (2, NBLK): halves adjacent
    //     so the second h1 tile read hits L2) + stats + per-node max/min
    gemm_mma<64, true, true, 4><<<dim3(2, NBLK), 256, ST64>>>(
        h1, wp2, nullptr, b2, bna, bnc, nullptr, mx, mn, psum, psq);
    stats_finalize<<<128, 256>>>(psum, psq, gm2, be2, bna, bnc);

    apply_out<<<(NNODES * 128) / 256, 256>>>(mx, mn, bna, bnc, out);
}

// round 11
// speedup vs baseline: 1.1075x; 1.1075x over previous
#include <cuda_runtime.h>
#include <cuda_bf16.h>
#include <math_constants.h>
#include <cstdint>

// ---------------------------------------------------------------------------
// PointNetConv via mma.sync bf16 m16n8k16, 3-term split (~1e-5 accuracy)
//   3x (1x1 conv -> BN(train) -> ReLU) -> max over K=64 neighbors
// Round-11: (1) revert occupancy experiment (MINBLK=3, 16-row prefetch,
// regs ~80 -> restores round-9 mainloop perf, keeps prep_w + 6-op split);
// (2) L2 N-halves merged into one COUT=128 CTA (warp tile 32x64): h1 tile is
// loaded + converted ONCE instead of twice; epilogue stats in two passes.
// ---------------------------------------------------------------------------

#define TOTAL_ROWS (16384 * 64)
#define NBLK       8192
#define NNODES     16384
#define EPS        1e-5f
#define PCOUNT     ((float)TOTAL_ROWS)

__device__ float g_h0[TOTAL_ROWS * 64];
__device__ float g_h1[TOTAL_ROWS * 64];
__device__ float g_mx[NNODES * 128];
__device__ float g_mn[NNODES * 128];
__device__ float g_psum[128 * NBLK];
__device__ float g_psq [128 * NBLK];
__device__ float g_bna[128];
__device__ float g_bnc[128];
__device__ uint2 g_wp0[64 * 32];     // pre-split W (bf16 hi/lo pairs)
__device__ uint2 g_wp1[64 * 32];
__device__ uint2 g_wp2[128 * 32];

#define AS 36   // A pair-stride (uint2): mod 16 = 4 -> conflict-free frags
#define BS 36   // B pair-stride (uint2)

// ---- smem layout ----
template <int CIN, int COUT> struct SmemOff {
    static constexpr int WE = 512;
    static constexpr int XE = 1536;
    static constexpr int A  = (CIN == 67) ? 3584 : 512;
    static constexpr int B  = A + 128 * AS * 8;
    static constexpr int TOTAL = B + COUT * BS * 8;
};

// fast split: two fp32 (k-even,k-odd) -> packed bf16x2 hi word + lo word
static __device__ __forceinline__ uint2 split2_bf16(float v0, float v1) {
    uint32_t hi, lo;
    asm("cvt.rn.bf16x2.f32 %0, %1, %2;" : "=r"(hi) : "f"(v1), "f"(v0));
    float r0 = v0 - __uint_as_float(hi << 16);          // exact residuals
    float r1 = v1 - __uint_as_float(hi & 0xFFFF0000u);
    asm("cvt.rn.bf16x2.f32 %0, %1, %2;" : "=r"(lo) : "f"(r1), "f"(r0));
    return make_uint2(hi, lo);
}

static __device__ __forceinline__ void mma_bf16(float* c, const uint32_t* a,
                                                const uint32_t* b) {
    asm volatile(
        "mma.sync.aligned.m16n8k16.row.col.f32.bf16.bf16.f32 "
        "{%0,%1,%2,%3}, {%4,%5,%6,%7}, {%8,%9}, {%0,%1,%2,%3};"
        : "+f"(c[0]), "+f"(c[1]), "+f"(c[2]), "+f"(c[3])
        : "r"(a[0]), "r"(a[1]), "r"(a[2]), "r"(a[3]), "r"(b[0]), "r"(b[1]));
}

// ---- tiny prep: split all weights once ----
__global__ void __launch_bounds__(256) prep_w(
    const float* __restrict__ W0, const float* __restrict__ W1,
    const float* __restrict__ W2,
    uint2* __restrict__ P0, uint2* __restrict__ P1, uint2* __restrict__ P2)
{
    int idx = blockIdx.x * 256 + threadIdx.x;
    if (idx < 64 * 32) {
        int o = idx >> 5, pr = idx & 31;
        P0[idx] = split2_bf16(W0[o * 67 + 2 * pr], W0[o * 67 + 2 * pr + 1]);
    } else if (idx < 128 * 32) {
        int j = idx - 64 * 32;
        int o = j >> 5, pr = j & 31;
        float2 v = *(const float2*)&W1[o * 64 + 2 * pr];
        P1[j] = split2_bf16(v.x, v.y);
    } else if (idx < 256 * 32) {
        int j = idx - 128 * 32;
        int o = j >> 5, pr = j & 31;
        float2 v = *(const float2*)&W2[o * 64 + 2 * pr];
        P2[j] = split2_bf16(v.x, v.y);
    }
}

// ---------------------------------------------------------------------------
template <int CIN, int COUT, bool BN_IN, bool REDUCE, int MINBLK>
__global__ void __launch_bounds__(256, MINBLK) gemm_mma(
    const float* __restrict__ X, const uint2* __restrict__ Wp,
    const float* __restrict__ Wraw,            // only for CIN==67 extras
    const float* __restrict__ B,
    const float* __restrict__ bna, const float* __restrict__ bnc,
    float* __restrict__ H, float* __restrict__ mxout, float* __restrict__ mnout,
    float* __restrict__ psum, float* __restrict__ psq)
{
    using SO = SmemOff<CIN, COUT>;
    constexpr int NT = COUT / 16;     // n-tiles per warp (4 or 8)
    constexpr int NW = COUT / 8;      // W rows per thread batch
    extern __shared__ char smem[];
    float* Bsm = (float*)(smem);                 // COUT f
    float* We  = (float*)(smem + SO::WE);
    float* Xe  = (float*)(smem + SO::XE);
    uint2* Ap  = (uint2*)(smem + SO::A);         // [128][AS]
    uint2* Bp  = (uint2*)(smem + SO::B);         // [COUT][BS]
    // epilogue buffers overlay dead A region (guarded by syncthreads)
    float* Ps  = (float*)(smem + SO::A);         // [4][COUT]
    float* Pq  = (float*)(smem + SO::A + 2048);
    float* Mxs = (float*)(smem + SO::A + 4096);
    float* Mns = (float*)(smem + SO::A + 6144);

    const int tid  = threadIdx.x;
    const int wid  = tid >> 5;
    const int lane = tid & 31;
    const int q = lane >> 2, s = lane & 3;
    const int bx = blockIdx.x;
    const int ob = blockIdx.y * 64;              // 0 except legacy split use
    const long long row0 = (long long)bx * 128;
    const int rg = wid;
    const int l2 = 2 * lane;

    if (tid < COUT) Bsm[tid] = B[ob + tid];

    float ba0 = 0.f, ba1 = 0.f, bc0 = 0.f, bc1 = 0.f;
    if (BN_IN) {
        float2 t = *(const float2*)&bna[l2];
        float2 u = *(const float2*)&bnc[l2];
        ba0 = t.x; ba1 = t.y; bc0 = u.x; bc1 = u.y;
    }

    // ---- W: copy pre-split pairs (rows rg + 8i, pr = lane) ----
    {
        uint2 wv[NW];
#pragma unroll
        for (int i = 0; i < NW; i++)
            wv[i] = Wp[(ob + rg + 8 * i) * 32 + lane];
#pragma unroll
        for (int i = 0; i < NW; i++)
            Bp[(rg + 8 * i) * BS + lane] = wv[i];
    }

    // ---- X -> Ap pairs: single 16-row prefetch batch (MLP=16) ----
    {
        float xv0[16], xv1[16];
#pragma unroll
        for (int i = 0; i < 16; i++) {
            int r = rg + 8 * i;
            if (CIN == 64) {
                float2 v = *(const float2*)&X[(row0 + r) * 64 + l2];
                xv0[i] = v.x; xv1[i] = v.y;
            } else {
                xv0[i] = X[(row0 + r) * CIN + l2];
                xv1[i] = X[(row0 + r) * CIN + l2 + 1];
            }
        }
#pragma unroll
        for (int i = 0; i < 16; i++) {
            float v0 = xv0[i], v1 = xv1[i];
            if (BN_IN) {
                v0 = fmaxf(fmaf(ba0, v0, bc0), 0.0f);
                v1 = fmaxf(fmaf(ba1, v1, bc1), 0.0f);
            }
            Ap[(rg + 8 * i) * AS + lane] = split2_bf16(v0, v1);
        }
    }
    if (CIN == 67) {
        for (int p = tid; p < 64 * 4; p += 256) {
            int o = p >> 2, j = p & 3;
            We[p] = (j < 3) ? Wraw[(ob + o) * 67 + 64 + j] : 0.0f;
        }
        for (int p = tid; p < 128 * 4; p += 256) {
            int r = p >> 2, j = p & 3;
            Xe[p] = (j < 3) ? X[(row0 + r) * 67 + 64 + j] : 0.0f;
        }
    }
    __syncthreads();

    // ---- MMA mainloop: warp tile 32 x (COUT/2), K=64 in 4 k16-steps ----
    const int wr = (wid >> 1) * 32;
    const int wc = (wid & 1) * (COUT / 2);

    float acc[2 * NT][4];
#pragma unroll
    for (int t = 0; t < 2 * NT; t++)
#pragma unroll
        for (int j = 0; j < 4; j++) acc[t][j] = 0.0f;

#pragma unroll
    for (int kk = 0; kk < 4; kk++) {
        const int pb = kk * 8 + s;
        uint32_t ah[2][4], al[2][4];
#pragma unroll
        for (int mt = 0; mt < 2; mt++) {
            int r0 = wr + mt * 16 + q;
            uint2 a0 = Ap[(r0    ) * AS + pb];
            uint2 a1 = Ap[(r0 + 8) * AS + pb];
            uint2 a2 = Ap[(r0    ) * AS + pb + 4];
            uint2 a3 = Ap[(r0 + 8) * AS + pb + 4];
            ah[mt][0] = a0.x; al[mt][0] = a0.y;
            ah[mt][1] = a1.x; al[mt][1] = a1.y;
            ah[mt][2] = a2.x; al[mt][2] = a2.y;
            ah[mt][3] = a3.x; al[mt][3] = a3.y;
        }
#pragma unroll
        for (int nt = 0; nt < NT; nt++) {
            int n = wc + nt * 8 + q;
            uint2 b0 = Bp[n * BS + pb];
            uint2 b1 = Bp[n * BS + pb + 4];
            uint32_t bh[2] = {b0.x, b1.x};
            uint32_t bl[2] = {b0.y, b1.y};
#pragma unroll
            for (int mt = 0; mt < 2; mt++) {
                mma_bf16(acc[mt * NT + nt], ah[mt], bh);
                mma_bf16(acc[mt * NT + nt], al[mt], bh);
                mma_bf16(acc[mt * NT + nt], ah[mt], bl);
            }
        }
    }

    __syncthreads();   // A region dead -> overlay Ps/Pq/Mxs/Mns

    // ---- epilogue in passes of 4 n-tiles (bounds stats register use) ----
    const int wr_idx = wid >> 1;
#pragma unroll
    for (int pass = 0; pass < NT / 4; pass++) {
        float ps[8], pq[8], mxv[8], mnv[8];
#pragma unroll
        for (int t = 0; t < 8; t++) {
            ps[t] = 0.0f; pq[t] = 0.0f;
            mxv[t] = -CUDART_INF_F; mnv[t] = CUDART_INF_F;
        }
#pragma unroll
        for (int mt = 0; mt < 2; mt++) {
#pragma unroll
            for (int h = 0; h < 2; h++) {
                int r = wr + mt * 16 + q + h * 8;
                float4 xe = make_float4(0.f, 0.f, 0.f, 0.f);
                if (CIN == 67) xe = *(float4*)&Xe[r * 4];
#pragma unroll
                for (int j = 0; j < 4; j++) {
                    int nt = pass * 4 + j;
                    int cb = wc + nt * 8 + 2 * s;
                    float v0 = acc[mt * NT + nt][h * 2 + 0] + Bsm[cb];
                    float v1 = acc[mt * NT + nt][h * 2 + 1] + Bsm[cb + 1];
                    if (CIN == 67) {
                        float4 w0 = *(float4*)&We[cb * 4];
                        float4 w1 = *(float4*)&We[(cb + 1) * 4];
                        v0 += w0.x * xe.x + w0.y * xe.y + w0.z * xe.z;
                        v1 += w1.x * xe.x + w1.y * xe.y + w1.z * xe.z;
                    }
                    if (!REDUCE)
                        *(float2*)&H[(row0 + r) * 64 + cb] = make_float2(v0, v1);
                    int t0 = j * 2, t1 = j * 2 + 1;
                    ps[t0] += v0; pq[t0] += v0 * v0;
                    ps[t1] += v1; pq[t1] += v1 * v1;
                    if (REDUCE) {
                        mxv[t0] = fmaxf(mxv[t0], v0); mnv[t0] = fminf(mnv[t0], v0);
                        mxv[t1] = fmaxf(mxv[t1], v1); mnv[t1] = fminf(mnv[t1], v1);
                    }
                }
            }
        }
        // warp reduce over q (offsets 16, 8, 4)
#pragma unroll
        for (int off = 16; off >= 4; off >>= 1) {
#pragma unroll
            for (int t = 0; t < 8; t++) {
                ps[t] += __shfl_down_sync(0xffffffffu, ps[t], off);
                pq[t] += __shfl_down_sync(0xffffffffu, pq[t], off);
                if (REDUCE) {
                    mxv[t] = fmaxf(mxv[t], __shfl_down_sync(0xffffffffu, mxv[t], off));
                    mnv[t] = fminf(mnv[t], __shfl_down_sync(0xffffffffu, mnv[t], off));
                }
            }
        }
        if (q == 0) {
#pragma unroll
            for (int t = 0; t < 8; t++) {
                int c = wc + (pass * 4 + (t >> 1)) * 8 + 2 * s + (t & 1);
                Ps[wr_idx * COUT + c] = ps[t];
                Pq[wr_idx * COUT + c] = pq[t];
                if (REDUCE) {
                    Mxs[wr_idx * COUT + c] = mxv[t];
                    Mns[wr_idx * COUT + c] = mnv[t];
                }
            }
        }
    }
    __syncthreads();

    if (tid < COUT) {
        float sa = Ps[tid] + Ps[COUT + tid] + Ps[2 * COUT + tid] + Ps[3 * COUT + tid];
        float qa = Pq[tid] + Pq[COUT + tid] + Pq[2 * COUT + tid] + Pq[3 * COUT + tid];
        psum[(ob + tid) * NBLK + bx] = sa;
        psq [(ob + tid) * NBLK + bx] = qa;
    }
    if (REDUCE) {
        // COUT=128: 256 threads cover 2 nodes x 128 channels.
        // row groups 0,1 (rows 0-63) -> node A; 2,3 -> node B.
        int half = tid >> 7, c = tid & 127;
        float mx = fmaxf(Mxs[(half * 2) * COUT + c], Mxs[(half * 2 + 1) * COUT + c]);
        float mn = fminf(Mns[(half * 2) * COUT + c], Mns[(half * 2 + 1) * COUT + c]);
        int node = bx * 2 + half;
        mxout[node * 128 + c] = mx;
        mnout[node * 128 + c] = mn;
    }
}

// ---------------------------------------------------------------------------
__global__ void __launch_bounds__(256) stats_finalize(
    const float* __restrict__ psum, const float* __restrict__ psq,
    const float* __restrict__ gamma, const float* __restrict__ beta,
    float* __restrict__ bna, float* __restrict__ bnc)
{
    const int o = blockIdx.x;
    const int tid = threadIdx.x;
    float s = 0.0f, q = 0.0f;
    for (int b = tid; b < NBLK; b += 256) {
        s += psum[o * NBLK + b];
        q += psq [o * NBLK + b];
    }
    __shared__ float sh[512];
    sh[tid] = s; sh[256 + tid] = q;
    __syncthreads();
    for (int st = 128; st > 0; st >>= 1) {
        if (tid < st) {
            sh[tid]       += sh[tid + st];
            sh[256 + tid] += sh[256 + tid + st];
        }
        __syncthreads();
    }
    if (tid == 0) {
        float mean = sh[0] / PCOUNT;
        float var  = sh[256] / PCOUNT - mean * mean;
        float a    = gamma[o] * rsqrtf(var + EPS);
        bna[o] = a;
        bnc[o] = beta[o] - mean * a;
    }
}

__global__ void __launch_bounds__(256) apply_out(
    const float* __restrict__ mx, const float* __restrict__ mn,
    const float* __restrict__ bna, const float* __restrict__ bnc,
    float* __restrict__ out)
{
    int idx = blockIdx.x * 256 + threadIdx.x;
    int c = idx & 127;
    float a = bna[c];
    float h = (a > 0.0f) ? mx[idx] : mn[idx];
    out[idx] = fmaxf(fmaf(a, h, bnc[c]), 0.0f);
}

// ---------------------------------------------------------------------------
extern "C" void kernel_launch(void* const* d_in, const int* in_sizes, int n_in,
                              void* d_out, int out_size)
{
    const float* x   = (const float*)d_in[0];
    const float* w0  = (const float*)d_in[1];
    const float* b0  = (const float*)d_in[2];
    const float* gm0 = (const float*)d_in[3];
    const float* be0 = (const float*)d_in[4];
    const float* w1  = (const float*)d_in[5];
    const float* b1  = (const float*)d_in[6];
    const float* gm1 = (const float*)d_in[7];
    const float* be1 = (const float*)d_in[8];
    const float* w2  = (const float*)d_in[9];
    const float* b2  = (const float*)d_in[10];
    const float* gm2 = (const float*)d_in[11];
    const float* be2 = (const float*)d_in[12];
    float* out = (float*)d_out;

    float *h0, *h1, *mx, *mn, *psum, *psq, *bna, *bnc;
    uint2 *wp0, *wp1, *wp2;
    cudaGetSymbolAddress((void**)&h0,   g_h0);
    cudaGetSymbolAddress((void**)&h1,   g_h1);
    cudaGetSymbolAddress((void**)&mx,   g_mx);
    cudaGetSymbolAddress((void**)&mn,   g_mn);
    cudaGetSymbolAddress((void**)&psum, g_psum);
    cudaGetSymbolAddress((void**)&psq,  g_psq);
    cudaGetSymbolAddress((void**)&bna,  g_bna);
    cudaGetSymbolAddress((void**)&bnc,  g_bnc);
    cudaGetSymbolAddress((void**)&wp0,  g_wp0);
    cudaGetSymbolAddress((void**)&wp1,  g_wp1);
    cudaGetSymbolAddress((void**)&wp2,  g_wp2);

    constexpr int ST0 = SmemOff<67, 64>::TOTAL;    // 58880 -> 3 CTAs/SM
    constexpr int ST1 = SmemOff<64, 64>::TOTAL;    // 55808 -> 3 CTAs/SM (regs)
    constexpr int ST2 = SmemOff<64, 128>::TOTAL;   // 74240 -> 2 CTAs/SM
    cudaFuncSetAttribute(gemm_mma<67, 64, false, false, 3>,
                         cudaFuncAttributeMaxDynamicSharedMemorySize, ST0);
    cudaFuncSetAttribute(gemm_mma<64, 64, true, false, 3>,
                         cudaFuncAttributeMaxDynamicSharedMemorySize, ST1);
    cudaFuncSetAttribute(gemm_mma<64, 128, true, true, 2>,
                         cudaFuncAttributeMaxDynamicSharedMemorySize, ST2);

    // launch #1: pre-split weights (also shifts ncu -s 5 onto merged L2)
    prep_w<<<32, 256>>>(w0, w1, w2, wp0, wp1, wp2);

    // L0: conv(67->64) + stats
    gemm_mma<67, 64, false, false, 3><<<dim3(NBLK, 1), 256, ST0>>>(
        x, wp0, w0, b0, nullptr, nullptr, h0, nullptr, nullptr, psum, psq);
    stats_finalize<<<64, 256>>>(psum, psq, gm0, be0, bna, bnc);

    // L1: bn0+relu on load -> conv(64->64) + stats
    gemm_mma<64, 64, true, false, 3><<<dim3(NBLK, 1), 256, ST1>>>(
        h0, wp1, nullptr, b1, bna, bnc, h1, nullptr, nullptr, psum, psq);
    stats_finalize<<<64, 256>>>(psum, psq, gm1, be1, bna, bnc);

    // L2 merged: bn1+relu on load -> conv(64->128) in ONE CTA per row tile
    //            (h1 converted once) + stats + per-node max/min
    gemm_mma<64, 128, true, true, 2><<<NBLK, 256, ST2>>>(
        h1, wp2, nullptr, b2, bna, bnc, nullptr, mx, mn, psum, psq);
    stats_finalize<<<128, 256>>>(psum, psq, gm2, be2, bna, bnc);

    apply_out<<<(NNODES * 128) / 256, 256>>>(mx, mn, bna, bnc, out);
}

// round 14
// speedup vs baseline: 1.1271x; 1.0177x over previous
#include <cuda_runtime.h>
#include <cuda_bf16.h>
#include <math_constants.h>
#include <cstdint>

// ---------------------------------------------------------------------------
// PointNetConv via mma.sync bf16 m16n8k16, 3-term split (~1e-5 accuracy)
//   3x (1x1 conv -> BN(train) -> ReLU) -> max over K=64 neighbors
// Round-12: (1) quad-width convert: LDG.128/STS.128 per channel-quad (halves
// convert-phase instructions + addressing ALU); (2) bias removed from GEMM:
// stats/max on raw accumulators; stats_finalize's shift c = beta - a*S/P
// exactly cancels the missing bias in the consumer affine (proven algebra).
// ---------------------------------------------------------------------------

#define TOTAL_ROWS (16384 * 64)
#define NBLK       8192
#define NNODES     16384
#define EPS        1e-5f
#define PCOUNT     ((float)TOTAL_ROWS)

__device__ float g_h0[TOTAL_ROWS * 64];
__device__ float g_h1[TOTAL_ROWS * 64];
__device__ float g_mx[NNODES * 128];
__device__ float g_mn[NNODES * 128];
__device__ float g_psum[128 * NBLK];
__device__ float g_psq [128 * NBLK];
__device__ float g_bna[128];
__device__ float g_bnc[128];
__device__ uint2 g_wp0[64 * 32];     // pre-split W (bf16 hi/lo pairs)
__device__ uint2 g_wp1[64 * 32];
__device__ uint2 g_wp2[128 * 32];

#define AS 36   // A pair-stride (uint2): mod 16 = 4 -> conflict-free frags
#define BS 36   // B pair-stride (uint2)

// ---- smem layout ----
template <int CIN, int COUT> struct SmemOff {
    static constexpr int WE = 512;
    static constexpr int XE = 1536;
    static constexpr int A  = (CIN == 67) ? 3584 : 512;
    static constexpr int B  = A + 128 * AS * 8;
    static constexpr int TOTAL = B + COUT * BS * 8;
};

// fast split: two fp32 (k-even,k-odd) -> packed bf16x2 hi word + lo word
static __device__ __forceinline__ uint2 split2_bf16(float v0, float v1) {
    uint32_t hi, lo;
    asm("cvt.rn.bf16x2.f32 %0, %1, %2;" : "=r"(hi) : "f"(v1), "f"(v0));
    float r0 = v0 - __uint_as_float(hi << 16);          // exact residuals
    float r1 = v1 - __uint_as_float(hi & 0xFFFF0000u);
    asm("cvt.rn.bf16x2.f32 %0, %1, %2;" : "=r"(lo) : "f"(r1), "f"(r0));
    return make_uint2(hi, lo);
}

static __device__ __forceinline__ void mma_bf16(float* c, const uint32_t* a,
                                                const uint32_t* b) {
    asm volatile(
        "mma.sync.aligned.m16n8k16.row.col.f32.bf16.bf16.f32 "
        "{%0,%1,%2,%3}, {%4,%5,%6,%7}, {%8,%9}, {%0,%1,%2,%3};"
        : "+f"(c[0]), "+f"(c[1]), "+f"(c[2]), "+f"(c[3])
        : "r"(a[0]), "r"(a[1]), "r"(a[2]), "r"(a[3]), "r"(b[0]), "r"(b[1]));
}

// ---- tiny prep: split all weights once ----
__global__ void __launch_bounds__(256) prep_w(
    const float* __restrict__ W0, const float* __restrict__ W1,
    const float* __restrict__ W2,
    uint2* __restrict__ P0, uint2* __restrict__ P1, uint2* __restrict__ P2)
{
    int idx = blockIdx.x * 256 + threadIdx.x;
    if (idx < 64 * 32) {
        int o = idx >> 5, pr = idx & 31;
        P0[idx] = split2_bf16(W0[o * 67 + 2 * pr], W0[o * 67 + 2 * pr + 1]);
    } else if (idx < 128 * 32) {
        int j = idx - 64 * 32;
        int o = j >> 5, pr = j & 31;
        float2 v = *(const float2*)&W1[o * 64 + 2 * pr];
        P1[j] = split2_bf16(v.x, v.y);
    } else if (idx < 256 * 32) {
        int j = idx - 128 * 32;
        int o = j >> 5, pr = j & 31;
        float2 v = *(const float2*)&W2[o * 64 + 2 * pr];
        P2[j] = split2_bf16(v.x, v.y);
    }
}

// ---------------------------------------------------------------------------
template <int CIN, int COUT, bool BN_IN, bool REDUCE, int MINBLK>
__global__ void __launch_bounds__(256, MINBLK) gemm_mma(
    const float* __restrict__ X, const uint2* __restrict__ Wp,
    const float* __restrict__ Wraw,            // only for CIN==67 extras
    const float* __restrict__ bna, const float* __restrict__ bnc,
    float* __restrict__ H, float* __restrict__ mxout, float* __restrict__ mnout,
    float* __restrict__ psum, float* __restrict__ psq)
{
    using SO = SmemOff<CIN, COUT>;
    constexpr int NT = COUT / 16;     // n-tiles per warp (4 or 8)
    extern __shared__ char smem[];
    float* We  = (float*)(smem + SO::WE);
    float* Xe  = (float*)(smem + SO::XE);
    uint2* Ap  = (uint2*)(smem + SO::A);         // [128][AS]
    uint2* Bp  = (uint2*)(smem + SO::B);         // [COUT][BS]
    // epilogue buffers overlay dead A region (guarded by syncthreads)
    float* Ps  = (float*)(smem + SO::A);         // [4][COUT]
    float* Pq  = (float*)(smem + SO::A + 2048);
    float* Mxs = (float*)(smem + SO::A + 4096);
    float* Mns = (float*)(smem + SO::A + 6144);

    const int tid  = threadIdx.x;
    const int wid  = tid >> 5;
    const int lane = tid & 31;
    const int q = lane >> 2, s = lane & 3;
    const int bx = blockIdx.x;
    const int ob = 0;
    const long long row0 = (long long)bx * 128;
    const int qd  = tid & 15;         // channel quad (loop-invariant)
    const int rgq = tid >> 4;         // row group for quad loops (0..15)

    // BN affine for this thread's fixed channel quad
    float4 baq = make_float4(0.f, 0.f, 0.f, 0.f);
    float4 bcq = make_float4(0.f, 0.f, 0.f, 0.f);
    if (BN_IN) {
        baq = *(const float4*)&bna[4 * qd];
        bcq = *(const float4*)&bnc[4 * qd];
    }

    // ---- W: copy pre-split pairs quad-wide (rows rgq + 16i) ----
    {
        const uint4* Wp4 = (const uint4*)Wp;
        uint4 wv[COUT / 16];
#pragma unroll
        for (int i = 0; i < COUT / 16; i++)
            wv[i] = Wp4[(ob + rgq + 16 * i) * 16 + qd];
#pragma unroll
        for (int i = 0; i < COUT / 16; i++)
            *(uint4*)&Bp[(rgq + 16 * i) * BS + 2 * qd] = wv[i];
    }

    // ---- X -> Ap: 8 quad-rows per thread, batched LDG.128 (MLP=8x16B) ----
    {
        float4 xv[8];
#pragma unroll
        for (int i = 0; i < 8; i++) {
            int r = rgq + 16 * i;
            if (CIN == 64) {
                xv[i] = *(const float4*)&X[(row0 + r) * 64 + 4 * qd];
            } else {
                const float* p = &X[(row0 + r) * 67 + 4 * qd];
                xv[i] = make_float4(p[0], p[1], p[2], p[3]);
            }
        }
#pragma unroll
        for (int i = 0; i < 8; i++) {
            float v0 = xv[i].x, v1 = xv[i].y, v2 = xv[i].z, v3 = xv[i].w;
            if (BN_IN) {
                v0 = fmaxf(fmaf(baq.x, v0, bcq.x), 0.0f);
                v1 = fmaxf(fmaf(baq.y, v1, bcq.y), 0.0f);
                v2 = fmaxf(fmaf(baq.z, v2, bcq.z), 0.0f);
                v3 = fmaxf(fmaf(baq.w, v3, bcq.w), 0.0f);
            }
            uint2 p0 = split2_bf16(v0, v1);
            uint2 p1 = split2_bf16(v2, v3);
            *(uint4*)&Ap[(rgq + 16 * i) * AS + 2 * qd] =
                make_uint4(p0.x, p0.y, p1.x, p1.y);
        }
    }
    if (CIN == 67) {
        for (int p = tid; p < 64 * 4; p += 256) {
            int o = p >> 2, j = p & 3;
            We[p] = (j < 3) ? Wraw[(ob + o) * 67 + 64 + j] : 0.0f;
        }
        for (int p = tid; p < 128 * 4; p += 256) {
            int r = p >> 2, j = p & 3;
            Xe[p] = (j < 3) ? X[(row0 + r) * 67 + 64 + j] : 0.0f;
        }
    }
    __syncthreads();

    // ---- MMA mainloop: warp tile 32 x (COUT/2), K=64 in 4 k16-steps ----
    const int wr = (wid >> 1) * 32;
    const int wc = (wid & 1) * (COUT / 2);

    float acc[2 * NT][4];
#pragma unroll
    for (int t = 0; t < 2 * NT; t++)
#pragma unroll
        for (int j = 0; j < 4; j++) acc[t][j] = 0.0f;

#pragma unroll
    for (int kk = 0; kk < 4; kk++) {
        const int pb = kk * 8 + s;
        uint32_t ah[2][4], al[2][4];
#pragma unroll
        for (int mt = 0; mt < 2; mt++) {
            int r0 = wr + mt * 16 + q;
            uint2 a0 = Ap[(r0    ) * AS + pb];
            uint2 a1 = Ap[(r0 + 8) * AS + pb];
            uint2 a2 = Ap[(r0    ) * AS + pb + 4];
            uint2 a3 = Ap[(r0 + 8) * AS + pb + 4];
            ah[mt][0] = a0.x; al[mt][0] = a0.y;
            ah[mt][1] = a1.x; al[mt][1] = a1.y;
            ah[mt][2] = a2.x; al[mt][2] = a2.y;
            ah[mt][3] = a3.x; al[mt][3] = a3.y;
        }
#pragma unroll
        for (int nt = 0; nt < NT; nt++) {
            int n = wc + nt * 8 + q;
            uint2 b0 = Bp[n * BS + pb];
            uint2 b1 = Bp[n * BS + pb + 4];
            uint32_t bh[2] = {b0.x, b1.x};
            uint32_t bl[2] = {b0.y, b1.y};
#pragma unroll
            for (int mt = 0; mt < 2; mt++) {
                mma_bf16(acc[mt * NT + nt], ah[mt], bh);
                mma_bf16(acc[mt * NT + nt], al[mt], bh);
                mma_bf16(acc[mt * NT + nt], ah[mt], bl);
            }
        }
    }

    __syncthreads();   // A region dead -> overlay Ps/Pq/Mxs/Mns

    // ---- epilogue: raw acc (+L0 exact extras), stats, max/min, H store ----
    // NOTE: bias deliberately NOT added. stats_finalize computes
    // c = beta - a*S/P from raw sums, which exactly cancels the missing bias
    // in the consumer's a*h + c (and in apply_out).
    const int wr_idx = wid >> 1;
#pragma unroll
    for (int pass = 0; pass < NT / 4; pass++) {
        float ps[8], pq[8], mxv[8], mnv[8];
#pragma unroll
        for (int t = 0; t < 8; t++) {
            ps[t] = 0.0f; pq[t] = 0.0f;
            mxv[t] = -CUDART_INF_F; mnv[t] = CUDART_INF_F;
        }
#pragma unroll
        for (int mt = 0; mt < 2; mt++) {
#pragma unroll
            for (int h = 0; h < 2; h++) {
                int r = wr + mt * 16 + q + h * 8;
                float4 xe = make_float4(0.f, 0.f, 0.f, 0.f);
                if (CIN == 67) xe = *(float4*)&Xe[r * 4];
#pragma unroll
                for (int j = 0; j < 4; j++) {
                    int nt = pass * 4 + j;
                    int cb = wc + nt * 8 + 2 * s;
                    float v0 = acc[mt * NT + nt][h * 2 + 0];
                    float v1 = acc[mt * NT + nt][h * 2 + 1];
                    if (CIN == 67) {
                        float4 w0 = *(float4*)&We[cb * 4];
                        float4 w1 = *(float4*)&We[(cb + 1) * 4];
                        v0 += w0.x * xe.x + w0.y * xe.y + w0.z * xe.z;
                        v1 += w1.x * xe.x + w1.y * xe.y + w1.z * xe.z;
                    }
                    if (!REDUCE)
                        *(float2*)&H[(row0 + r) * 64 + cb] = make_float2(v0, v1);
                    int t0 = j * 2, t1 = j * 2 + 1;
                    ps[t0] += v0; pq[t0] += v0 * v0;
                    ps[t1] += v1; pq[t1] += v1 * v1;
                    if (REDUCE) {
                        mxv[t0] = fmaxf(mxv[t0], v0); mnv[t0] = fminf(mnv[t0], v0);
                        mxv[t1] = fmaxf(mxv[t1], v1); mnv[t1] = fminf(mnv[t1], v1);
                    }
                }
            }
        }
        // warp reduce over q (offsets 16, 8, 4)
#pragma unroll
        for (int off = 16; off >= 4; off >>= 1) {
#pragma unroll
            for (int t = 0; t < 8; t++) {
                ps[t] += __shfl_down_sync(0xffffffffu, ps[t], off);
                pq[t] += __shfl_down_sync(0xffffffffu, pq[t], off);
                if (REDUCE) {
                    mxv[t] = fmaxf(mxv[t], __shfl_down_sync(0xffffffffu, mxv[t], off));
                    mnv[t] = fminf(mnv[t], __shfl_down_sync(0xffffffffu, mnv[t], off));
                }
            }
        }
        if (q == 0) {
#pragma unroll
            for (int t = 0; t < 8; t++) {
                int c = wc + (pass * 4 + (t >> 1)) * 8 + 2 * s + (t & 1);
                Ps[wr_idx * COUT + c] = ps[t];
                Pq[wr_idx * COUT + c] = pq[t];
                if (REDUCE) {
                    Mxs[wr_idx * COUT + c] = mxv[t];
                    Mns[wr_idx * COUT + c] = mnv[t];
                }
            }
        }
    }
    __syncthreads();

    if (tid < COUT) {
        float sa = Ps[tid] + Ps[COUT + tid] + Ps[2 * COUT + tid] + Ps[3 * COUT + tid];
        float qa = Pq[tid] + Pq[COUT + tid] + Pq[2 * COUT + tid] + Pq[3 * COUT + tid];
        psum[(ob + tid) * NBLK + bx] = sa;
        psq [(ob + tid) * NBLK + bx] = qa;
    }
    if (REDUCE) {
        // COUT=128: 256 threads cover 2 nodes x 128 channels.
        int half = tid >> 7, c = tid & 127;
        float mx = fmaxf(Mxs[(half * 2) * COUT + c], Mxs[(half * 2 + 1) * COUT + c]);
        float mn = fminf(Mns[(half * 2) * COUT + c], Mns[(half * 2 + 1) * COUT + c]);
        int node = bx * 2 + half;
        mxout[node * 128 + c] = mx;
        mnout[node * 128 + c] = mn;
    }
}

// ---------------------------------------------------------------------------
__global__ void __launch_bounds__(256) stats_finalize(
    const float* __restrict__ psum, const float* __restrict__ psq,
    const float* __restrict__ gamma, const float* __restrict__ beta,
    float* __restrict__ bna, float* __restrict__ bnc)
{
    const int o = blockIdx.x;
    const int tid = threadIdx.x;
    float s = 0.0f, q = 0.0f;
    for (int b = tid; b < NBLK; b += 256) {
        s += psum[o * NBLK + b];
        q += psq [o * NBLK + b];
    }
    __shared__ float sh[512];
    sh[tid] = s; sh[256 + tid] = q;
    __syncthreads();
    for (int st = 128; st > 0; st >>= 1) {
        if (tid < st) {
            sh[tid]       += sh[tid + st];
            sh[256 + tid] += sh[256 + tid + st];
        }
        __syncthreads();
    }
    if (tid == 0) {
        float mean = sh[0] / PCOUNT;             // raw-acc mean (bias folds out)
        float var  = sh[256] / PCOUNT - mean * mean;  // translation-invariant
        float a    = gamma[o] * rsqrtf(var + EPS);
        bna[o] = a;
        bnc[o] = beta[o] - mean * a;
    }
}

__global__ void __launch_bounds__(256) apply_out(
    const float* __restrict__ mx, const float* __restrict__ mn,
    const float* __restrict__ bna, const float* __restrict__ bnc,
    float* __restrict__ out)
{
    int idx = blockIdx.x * 256 + threadIdx.x;
    int c = idx & 127;
    float a = bna[c];
    float h = (a > 0.0f) ? mx[idx] : mn[idx];
    out[idx] = fmaxf(fmaf(a, h, bnc[c]), 0.0f);
}

// ---------------------------------------------------------------------------
extern "C" void kernel_launch(void* const* d_in, const int* in_sizes, int n_in,
                              void* d_out, int out_size)
{
    const float* x   = (const float*)d_in[0];
    const float* w0  = (const float*)d_in[1];
    const float* gm0 = (const float*)d_in[3];
    const float* be0 = (const float*)d_in[4];
    const float* w1  = (const float*)d_in[5];
    const float* gm1 = (const float*)d_in[7];
    const float* be1 = (const float*)d_in[8];
    const float* w2  = (const float*)d_in[9];
    const float* gm2 = (const float*)d_in[11];
    const float* be2 = (const float*)d_in[12];
    float* out = (float*)d_out;

    float *h0, *h1, *mx, *mn, *psum, *psq, *bna, *bnc;
    uint2 *wp0, *wp1, *wp2;
    cudaGetSymbolAddress((void**)&h0,   g_h0);
    cudaGetSymbolAddress((void**)&h1,   g_h1);
    cudaGetSymbolAddress((void**)&mx,   g_mx);
    cudaGetSymbolAddress((void**)&mn,   g_mn);
    cudaGetSymbolAddress((void**)&psum, g_psum);
    cudaGetSymbolAddress((void**)&psq,  g_psq);
    cudaGetSymbolAddress((void**)&bna,  g_bna);
    cudaGetSymbolAddress((void**)&bnc,  g_bnc);
    cudaGetSymbolAddress((void**)&wp0,  g_wp0);
    cudaGetSymbolAddress((void**)&wp1,  g_wp1);
    cudaGetSymbolAddress((void**)&wp2,  g_wp2);

    constexpr int ST0 = SmemOff<67, 64>::TOTAL;    // -> 3 CTAs/SM
    constexpr int ST1 = SmemOff<64, 64>::TOTAL;    // -> 3 CTAs/SM
    constexpr int ST2 = SmemOff<64, 128>::TOTAL;   // -> 2 CTAs/SM
    cudaFuncSetAttribute(gemm_mma<67, 64, false, false, 3>,
                         cudaFuncAttributeMaxDynamicSharedMemorySize, ST0);
    cudaFuncSetAttribute(gemm_mma<64, 64, true, false, 3>,
                         cudaFuncAttributeMaxDynamicSharedMemorySize, ST1);
    cudaFuncSetAttribute(gemm_mma<64, 128, true, true, 2>,
                         cudaFuncAttributeMaxDynamicSharedMemorySize, ST2);

    // launch #1: pre-split weights
    prep_w<<<32, 256>>>(w0, w1, w2, wp0, wp1, wp2);

    // L0: conv(67->64) raw + stats   (bias folded into downstream affine)
    gemm_mma<67, 64, false, false, 3><<<NBLK, 256, ST0>>>(
        x, wp0, w0, nullptr, nullptr, h0, nullptr, nullptr, psum, psq);
    stats_finalize<<<64, 256>>>(psum, psq, gm0, be0, bna, bnc);

    // L1: bn0+relu on load -> conv(64->64) raw + stats
    gemm_mma<64, 64, true, false, 3><<<NBLK, 256, ST1>>>(
        h0, wp1, nullptr, bna, bnc, h1, nullptr, nullptr, psum, psq);
    stats_finalize<<<64, 256>>>(psum, psq, gm1, be1, bna, bnc);

    // L2 merged: bn1+relu on load -> conv(64->128) raw, one CTA per row tile
    //            + stats + per-node max/min
    gemm_mma<64, 128, true, true, 2><<<NBLK, 256, ST2>>>(
        h1, wp2, nullptr, bna, bnc, nullptr, mx, mn, psum, psq);
    stats_finalize<<<128, 256>>>(psum, psq, gm2, be2, bna, bnc);

    apply_out<<<(NNODES * 128) / 256, 256>>>(mx, mn, bna, bnc, out);
}